// round 11
// baseline (speedup 1.0000x reference)
#include <cuda_runtime.h>
#include <cstdint>
#include <cstddef>

#define NN 100000
#define NE 1000000
#define HD 64
#define MD 64
#define NC 16

// ---------------- device scratch (no allocations allowed) ----------------
__device__ float g_agg[(size_t)NN * MD];   // 25.6 MB message accumulator
__device__ int   g_permA[NE];              // edges with type == true  (W0/b0)
__device__ int   g_permB[NE];              // edges with type == false (W1/b1)
__device__ int   g_cnt[4];                 // [0]=cntA [1]=cntB [2]=tilesA [3]=tilesB
__device__ int   g_is_byte;                // 1 if edge_types is 1-byte, 0 if int32

// ---------------- detect edge_types element width ------------------------
// bool(1B): ~50% of ALL bytes nonzero. int32(0/1): bytes at off%4!=0 are ALL 0.
// Reading 64KB as bytes is in-bounds under both interpretations (E=1e6 >= 65536).
__global__ void detect_k(const unsigned char* __restrict__ types) {
    __shared__ int found;
    if (threadIdx.x == 0) found = 0;
    __syncthreads();
    int loc = 0;
    for (int i = threadIdx.x; i < 65536; i += blockDim.x)
        if ((i & 3) != 0 && types[i] != 0) loc = 1;
    if (loc) found = 1;
    __syncthreads();
    if (threadIdx.x == 0) g_is_byte = found;
}

// ---------------- partition edges by type (warp-aggregated atomics) ------
__global__ void partition_k(const unsigned char* __restrict__ types) {
    int e = blockIdx.x * blockDim.x + threadIdx.x;
    bool valid = e < NE;
    int isb = g_is_byte;  // uniform
    bool ty = false;
    if (valid) {
        if (isb) ty = types[e] != 0;
        else     ty = reinterpret_cast<const int*>(types)[e] != 0;
    }
    unsigned mA = __ballot_sync(0xffffffffu, valid && ty);
    unsigned mB = __ballot_sync(0xffffffffu, valid && !ty);
    int lane = threadIdx.x & 31;
    int bA = 0, bB = 0;
    if (lane == 0) {
        bA = atomicAdd(&g_cnt[0], __popc(mA));
        bB = atomicAdd(&g_cnt[1], __popc(mB));
    }
    bA = __shfl_sync(0xffffffffu, bA, 0);
    bB = __shfl_sync(0xffffffffu, bB, 0);
    unsigned lt = (1u << lane) - 1u;
    if (valid) {
        if (ty) g_permA[bA + __popc(mA & lt)] = e;
        else    g_permB[bB + __popc(mB & lt)] = e;
    }
}

// pad each partition to a multiple of 64 with -1 sentinels; publish tile counts
__global__ void pad_k() {
    int t = threadIdx.x;  // 64 threads
    int cA = g_cnt[0], cB = g_cnt[1];
    int pA = (cA + 63) & ~63;   // NE % 64 == 0 so pA,pB <= NE
    int pB = (cB + 63) & ~63;
    if (cA + t < pA) g_permA[cA + t] = -1;
    if (cB + t < pB) g_permB[cB + t] = -1;
    if (t == 0) { g_cnt[2] = pA >> 6; g_cnt[3] = pB >> 6; }
}

// ---------------- edge message GEMM + scatter-add -----------------------
// One 64-edge tile per block iteration. 128 threads = 16 edge-rows x 8 out-cols.
// Thread computes 4 edges x 8 outputs (register blocked, 1.5 B LDS per FMA).
__global__ __launch_bounds__(128) void edge_msg_k(
    const float* __restrict__ feat, const int* __restrict__ src,
    const int* __restrict__ dst, const float* __restrict__ W,
    const float* __restrict__ b, int which)
{
    const int* perm = which ? g_permB : g_permA;
    int ntiles = g_cnt[which ? 3 : 2];
    if ((int)blockIdx.x >= ntiles) return;

    __shared__ float Wt[64][64];   // Wt[h][m]  (transposed weight)
    __shared__ float xs[64][64];   // xs[h][e]  (transposed gathered features)
    __shared__ int   eidx[64];
    __shared__ int   edst[64];

    int t   = threadIdx.x;
    int row = t & 15;        // edge group: edges row*4 .. row*4+3
    int col = t >> 4;        // output group: m = col*8 .. col*8+7

    // transpose W[m][h] -> Wt[h][m] (conflict-free: lanes store consecutive m)
    {
        int m = t & 63, hh = (t >> 6) * 32;
        const float4* wr = reinterpret_cast<const float4*>(W + m * 64 + hh);
#pragma unroll
        for (int q = 0; q < 8; q++) {
            float4 v = wr[q];
            int h = hh + q * 4;
            Wt[h][m] = v.x; Wt[h + 1][m] = v.y; Wt[h + 2][m] = v.z; Wt[h + 3][m] = v.w;
        }
    }
    float bias[8];
#pragma unroll
    for (int i = 0; i < 8; i++) bias[i] = b[col * 8 + i];

    for (int tile = blockIdx.x; tile < ntiles; tile += gridDim.x) {
        __syncthreads();   // protect eidx/xs from previous iteration readers
        if (t < 64) {
            int id = perm[tile * 64 + t];
            eidx[t] = id;
            edst[t] = (id >= 0) ? dst[id] : 0;
        }
        __syncthreads();

        // gather: thread covers edge e = t&63, h-half = (t>>6)*32, transposed store
        {
            int e = t & 63, hh = (t >> 6) * 32;
            int id = eidx[e];
            if (id >= 0) {
                const float4* xr =
                    reinterpret_cast<const float4*>(feat + (size_t)src[id] * 64 + hh);
#pragma unroll
                for (int q = 0; q < 8; q++) {
                    float4 v = xr[q];
                    int h = hh + q * 4;
                    xs[h][e] = v.x; xs[h + 1][e] = v.y; xs[h + 2][e] = v.z; xs[h + 3][e] = v.w;
                }
            } else {
#pragma unroll
                for (int q = 0; q < 8; q++) {
                    int h = hh + q * 4;
                    xs[h][e] = 0.f; xs[h + 1][e] = 0.f; xs[h + 2][e] = 0.f; xs[h + 3][e] = 0.f;
                }
            }
        }
        __syncthreads();

        float acc[4][8];
#pragma unroll
        for (int j = 0; j < 4; j++)
#pragma unroll
            for (int i = 0; i < 8; i++) acc[j][i] = bias[i];

#pragma unroll 4
        for (int h = 0; h < 64; h++) {
            float4 xv = *reinterpret_cast<const float4*>(&xs[h][row * 4]);
            float4 w0 = *reinterpret_cast<const float4*>(&Wt[h][col * 8]);
            float4 w1 = *reinterpret_cast<const float4*>(&Wt[h][col * 8 + 4]);
            float xj[4] = {xv.x, xv.y, xv.z, xv.w};
            float wi[8] = {w0.x, w0.y, w0.z, w0.w, w1.x, w1.y, w1.z, w1.w};
#pragma unroll
            for (int j = 0; j < 4; j++)
#pragma unroll
                for (int i = 0; i < 8; i++) acc[j][i] = fmaf(xj[j], wi[i], acc[j][i]);
        }

        // scatter-add into node accumulator (RED.ADD, result unused)
#pragma unroll
        for (int j = 0; j < 4; j++) {
            int e = row * 4 + j;
            if (eidx[e] >= 0) {
                float* p = g_agg + (size_t)edst[e] * 64 + col * 8;
#pragma unroll
                for (int i = 0; i < 8; i++) atomicAdd(p + i, acc[j][i]);
            }
        }
    }
}

// ---------------- fused GRU + classifier --------------------------------
// 32-node tiles. 192 threads = 4 node-rows (8 nodes each) x 48 out-cols (8 each).
// Outputs o<192 -> gi = W_ih @ agg ; o>=192 -> gh = W_hh @ features.
#define XA_S  65
#define GS_S  388
#define HS_S  65
#define WO_S  65

__global__ __launch_bounds__(192) void gru_out_k(
    const float* __restrict__ feat,
    const float* __restrict__ W_ih, const float* __restrict__ W_hh,
    const float* __restrict__ b_ih, const float* __restrict__ b_hh,
    const float* __restrict__ W_out, const float* __restrict__ b_out,
    float* __restrict__ out)
{
    extern __shared__ float smf[];
    float* Wct = smf;                     // [64][384]   transposed combined W
    float* xa  = Wct + 64 * 384;          // [32][65]    agg tile
    float* xf  = xa + 32 * XA_S;          // [32][65]    feature tile
    float* gs  = xf + 32 * XA_S;          // [32][388]   gate pre-activations
    float* hs  = gs + 32 * GS_S;          // [32][65]    new hidden
    float* Wos = hs + 32 * HS_S;          // [16][65]    classifier W
    float* bos = Wos + 16 * WO_S;         // [16]

    int t   = threadIdx.x;
    int row = t & 3;       // nodes row*8 .. row*8+7
    int col = t >> 2;      // outputs col*8 .. col*8+7  (col<24 -> gi, else gh)

    // load W_ih / W_hh transposed into Wct[h][o] (lanes store consecutive o)
#pragma unroll
    for (int rep = 0; rep < 2; rep++) {
        int o = t + rep * 192;
        const float* wr = (o < 192) ? (W_ih + o * 64) : (W_hh + (o - 192) * 64);
        const float4* wr4 = reinterpret_cast<const float4*>(wr);
#pragma unroll
        for (int q = 0; q < 16; q++) {
            float4 v = wr4[q];
            int h = q * 4;
            Wct[(h    ) * 384 + o] = v.x;
            Wct[(h + 1) * 384 + o] = v.y;
            Wct[(h + 2) * 384 + o] = v.z;
            Wct[(h + 3) * 384 + o] = v.w;
        }
    }
    for (int k = t; k < 1024; k += 192) {
        int c = k >> 6, d = k & 63;
        Wos[c * WO_S + d] = W_out[k];
    }
    if (t < 16) bos[t] = b_out[t];

    float bias8[8];
#pragma unroll
    for (int i = 0; i < 8; i++) {
        int o = col * 8 + i;
        bias8[i] = (o < 192) ? b_ih[o] : b_hh[o - 192];
    }

    const int ntiles = NN / 32;  // 3125
    for (int tile = blockIdx.x; tile < ntiles; tile += gridDim.x) {
        int nb = tile * 32;
        __syncthreads();  // protect xa/xf/gs/hs from previous iteration readers
        for (int k = t; k < 2048; k += 192) {
            int nl = k >> 6, h = k & 63;
            size_t gidx = (size_t)(nb + nl) * 64 + h;
            xa[nl * XA_S + h] = g_agg[gidx];
            xf[nl * XA_S + h] = feat[gidx];
        }
        __syncthreads();

        float acc[8][8];
#pragma unroll
        for (int k = 0; k < 8; k++)
#pragma unroll
            for (int i = 0; i < 8; i++) acc[k][i] = bias8[i];

        const float* xin = (col < 24) ? xa : xf;
#pragma unroll 2
        for (int h = 0; h < 64; h++) {
            float4 w0 = *reinterpret_cast<const float4*>(&Wct[h * 384 + col * 8]);
            float4 w1 = *reinterpret_cast<const float4*>(&Wct[h * 384 + col * 8 + 4]);
            float wv[8] = {w0.x, w0.y, w0.z, w0.w, w1.x, w1.y, w1.z, w1.w};
            float xk[8];
#pragma unroll
            for (int k = 0; k < 8; k++) xk[k] = xin[(row * 8 + k) * XA_S + h];
#pragma unroll
            for (int k = 0; k < 8; k++)
#pragma unroll
                for (int i = 0; i < 8; i++) acc[k][i] = fmaf(xk[k], wv[i], acc[k][i]);
        }

#pragma unroll
        for (int k = 0; k < 8; k++) {
            float* gp = &gs[(row * 8 + k) * GS_S + col * 8];
            *reinterpret_cast<float4*>(gp)     = make_float4(acc[k][0], acc[k][1], acc[k][2], acc[k][3]);
            *reinterpret_cast<float4*>(gp + 4) = make_float4(acc[k][4], acc[k][5], acc[k][6], acc[k][7]);
        }
        __syncthreads();

        // GRU gates: r,z,n ordering (torch convention)
        for (int k = t; k < 2048; k += 192) {
            int nl = k >> 6, d = k & 63;
            const float* g = &gs[nl * GS_S];
            float ir = g[d],       iz = g[64 + d],  in_ = g[128 + d];
            float hr = g[192 + d], hz = g[256 + d], hn  = g[320 + d];
            float r = 1.f / (1.f + __expf(-(ir + hr)));
            float z = 1.f / (1.f + __expf(-(iz + hz)));
            float nng = tanhf(in_ + r * hn);
            hs[nl * HS_S + d] = (1.f - z) * nng + z * xf[nl * XA_S + d];
        }
        __syncthreads();

        // classifier: out[n][c] = b_out[c] + W_out[c,:] . h[n,:]
        for (int k = t; k < 512; k += 192) {
            int nl = k >> 4, c = k & 15;
            const float* wrow = &Wos[c * WO_S];
            const float* hrow = &hs[nl * HS_S];
            float s = bos[c];
#pragma unroll
            for (int d = 0; d < 64; d++) s = fmaf(wrow[d], hrow[d], s);
            out[(size_t)(nb + nl) * 16 + c] = s;
        }
    }
}

// ---------------- launch -------------------------------------------------
extern "C" void kernel_launch(void* const* d_in, const int* in_sizes, int n_in,
                              void* d_out, int out_size) {
    const float*         feat  = (const float*)d_in[0];
    const int*           src   = (const int*)d_in[1];
    const int*           dst   = (const int*)d_in[2];
    const unsigned char* types = (const unsigned char*)d_in[3];
    const float*         W0    = (const float*)d_in[4];
    const float*         b0    = (const float*)d_in[5];
    const float*         W1    = (const float*)d_in[6];
    const float*         b1    = (const float*)d_in[7];
    const float*         W_ih  = (const float*)d_in[8];
    const float*         W_hh  = (const float*)d_in[9];
    const float*         b_ih  = (const float*)d_in[10];
    const float*         b_hh  = (const float*)d_in[11];
    const float*         W_out = (const float*)d_in[12];
    const float*         b_out = (const float*)d_in[13];
    float*               out   = (float*)d_out;

    (void)in_sizes; (void)n_in; (void)out_size;

    void* aggp = nullptr; void* cntp = nullptr;
    cudaGetSymbolAddress(&aggp, g_agg);
    cudaGetSymbolAddress(&cntp, g_cnt);
    cudaMemsetAsync(aggp, 0, sizeof(float) * (size_t)NN * MD);
    cudaMemsetAsync(cntp, 0, sizeof(int) * 4);

    int dev = 0, numSM = 148;
    cudaGetDevice(&dev);
    cudaDeviceGetAttribute(&numSM, cudaDevAttrMultiProcessorCount, dev);

    detect_k<<<1, 256>>>(types);
    partition_k<<<(NE + 255) / 256, 256>>>(types);
    pad_k<<<1, 64>>>();

    int egrid = numSM * 6;
    edge_msg_k<<<egrid, 128>>>(feat, src, dst, W0, b0, 0);  // type==true  -> W0/b0
    edge_msg_k<<<egrid, 128>>>(feat, src, dst, W1, b1, 1);  // type==false -> W1/b1

    const size_t smBytes =
        (size_t)(64 * 384 + 2 * 32 * XA_S + 32 * GS_S + 32 * HS_S + 16 * WO_S + 16) * 4;
    cudaFuncSetAttribute(gru_out_k, cudaFuncAttributeMaxDynamicSharedMemorySize,
                         (int)smBytes);
    gru_out_k<<<numSM, 192, smBytes>>>(feat, W_ih, W_hh, b_ih, b_hh, W_out, b_out, out);
}

// round 12
// speedup vs baseline: 1.0033x; 1.0033x over previous
#include <cuda_runtime.h>
#include <cstdint>
#include <cstddef>

#define NN 100000
#define NE 1000000
#define HD 64
#define MD 64
#define NC 16

// ---------------- device scratch (no allocations allowed) ----------------
__device__ float g_agg[(size_t)NN * MD];   // 25.6 MB message accumulator
__device__ int   g_permA[NE];              // edges with type == true  (W0/b0)
__device__ int   g_permB[NE];              // edges with type == false (W1/b1)
__device__ int   g_cnt[4];                 // [0]=cntA [1]=cntB [2]=tilesA [3]=tilesB
__device__ int   g_is_byte;                // 1 if edge_types is 1-byte, 0 if int32

// ---------------- detect edge_types element width ------------------------
// bool(1B): ~50% of ALL bytes nonzero. int32(0/1): bytes at off%4!=0 are ALL 0.
// Reading 64KB as bytes is in-bounds under both interpretations (E=1e6 >= 65536).
__global__ void detect_k(const unsigned char* __restrict__ types) {
    __shared__ int found;
    if (threadIdx.x == 0) found = 0;
    __syncthreads();
    int loc = 0;
    for (int i = threadIdx.x; i < 65536; i += blockDim.x)
        if ((i & 3) != 0 && types[i] != 0) loc = 1;
    if (loc) found = 1;
    __syncthreads();
    if (threadIdx.x == 0) g_is_byte = found;
}

// ---------------- partition edges by type (warp-aggregated atomics) ------
__global__ void partition_k(const unsigned char* __restrict__ types) {
    int e = blockIdx.x * blockDim.x + threadIdx.x;
    bool valid = e < NE;
    int isb = g_is_byte;  // uniform
    bool ty = false;
    if (valid) {
        if (isb) ty = types[e] != 0;
        else     ty = reinterpret_cast<const int*>(types)[e] != 0;
    }
    unsigned mA = __ballot_sync(0xffffffffu, valid && ty);
    unsigned mB = __ballot_sync(0xffffffffu, valid && !ty);
    int lane = threadIdx.x & 31;
    int bA = 0, bB = 0;
    if (lane == 0) {
        bA = atomicAdd(&g_cnt[0], __popc(mA));
        bB = atomicAdd(&g_cnt[1], __popc(mB));
    }
    bA = __shfl_sync(0xffffffffu, bA, 0);
    bB = __shfl_sync(0xffffffffu, bB, 0);
    unsigned lt = (1u << lane) - 1u;
    if (valid) {
        if (ty) g_permA[bA + __popc(mA & lt)] = e;
        else    g_permB[bB + __popc(mB & lt)] = e;
    }
}

// pad each partition to a multiple of 64 with -1 sentinels; publish tile counts
__global__ void pad_k() {
    int t = threadIdx.x;  // 64 threads
    int cA = g_cnt[0], cB = g_cnt[1];
    int pA = (cA + 63) & ~63;   // NE % 64 == 0 so pA,pB <= NE
    int pB = (cB + 63) & ~63;
    if (cA + t < pA) g_permA[cA + t] = -1;
    if (cB + t < pB) g_permB[cB + t] = -1;
    if (t == 0) { g_cnt[2] = pA >> 6; g_cnt[3] = pB >> 6; }
}

// ---------------- edge message GEMM + scatter-add -----------------------
// One 64-edge tile per block iteration. 128 threads = 16 edge-rows x 8 out-cols.
// Thread computes 4 edges x 8 outputs (register blocked, 1.5 B LDS per FMA).
__global__ __launch_bounds__(128) void edge_msg_k(
    const float* __restrict__ feat, const int* __restrict__ src,
    const int* __restrict__ dst, const float* __restrict__ W,
    const float* __restrict__ b, int which)
{
    const int* perm = which ? g_permB : g_permA;
    int ntiles = g_cnt[which ? 3 : 2];
    if ((int)blockIdx.x >= ntiles) return;

    __shared__ float Wt[64][64];   // Wt[h][m]  (transposed weight)
    __shared__ float xs[64][64];   // xs[h][e]  (transposed gathered features)
    __shared__ int   eidx[64];
    __shared__ int   edst[64];

    int t   = threadIdx.x;
    int row = t & 15;        // edge group: edges row*4 .. row*4+3
    int col = t >> 4;        // output group: m = col*8 .. col*8+7

    // transpose W[m][h] -> Wt[h][m] (conflict-free: lanes store consecutive m)
    {
        int m = t & 63, hh = (t >> 6) * 32;
        const float4* wr = reinterpret_cast<const float4*>(W + m * 64 + hh);
#pragma unroll
        for (int q = 0; q < 8; q++) {
            float4 v = wr[q];
            int h = hh + q * 4;
            Wt[h][m] = v.x; Wt[h + 1][m] = v.y; Wt[h + 2][m] = v.z; Wt[h + 3][m] = v.w;
        }
    }
    float bias[8];
#pragma unroll
    for (int i = 0; i < 8; i++) bias[i] = b[col * 8 + i];

    for (int tile = blockIdx.x; tile < ntiles; tile += gridDim.x) {
        __syncthreads();   // protect eidx/xs from previous iteration readers
        if (t < 64) {
            int id = perm[tile * 64 + t];
            eidx[t] = id;
            edst[t] = (id >= 0) ? dst[id] : 0;
        }
        __syncthreads();

        // gather: thread covers edge e = t&63, h-half = (t>>6)*32, transposed store
        {
            int e = t & 63, hh = (t >> 6) * 32;
            int id = eidx[e];
            if (id >= 0) {
                const float4* xr =
                    reinterpret_cast<const float4*>(feat + (size_t)src[id] * 64 + hh);
#pragma unroll
                for (int q = 0; q < 8; q++) {
                    float4 v = xr[q];
                    int h = hh + q * 4;
                    xs[h][e] = v.x; xs[h + 1][e] = v.y; xs[h + 2][e] = v.z; xs[h + 3][e] = v.w;
                }
            } else {
#pragma unroll
                for (int q = 0; q < 8; q++) {
                    int h = hh + q * 4;
                    xs[h][e] = 0.f; xs[h + 1][e] = 0.f; xs[h + 2][e] = 0.f; xs[h + 3][e] = 0.f;
                }
            }
        }
        __syncthreads();

        float acc[4][8];
#pragma unroll
        for (int j = 0; j < 4; j++)
#pragma unroll
            for (int i = 0; i < 8; i++) acc[j][i] = bias[i];

#pragma unroll 4
        for (int h = 0; h < 64; h++) {
            float4 xv = *reinterpret_cast<const float4*>(&xs[h][row * 4]);
            float4 w0 = *reinterpret_cast<const float4*>(&Wt[h][col * 8]);
            float4 w1 = *reinterpret_cast<const float4*>(&Wt[h][col * 8 + 4]);
            float xj[4] = {xv.x, xv.y, xv.z, xv.w};
            float wi[8] = {w0.x, w0.y, w0.z, w0.w, w1.x, w1.y, w1.z, w1.w};
#pragma unroll
            for (int j = 0; j < 4; j++)
#pragma unroll
                for (int i = 0; i < 8; i++) acc[j][i] = fmaf(xj[j], wi[i], acc[j][i]);
        }

        // scatter-add into node accumulator (RED.ADD, result unused)
#pragma unroll
        for (int j = 0; j < 4; j++) {
            int e = row * 4 + j;
            if (eidx[e] >= 0) {
                float* p = g_agg + (size_t)edst[e] * 64 + col * 8;
#pragma unroll
                for (int i = 0; i < 8; i++) atomicAdd(p + i, acc[j][i]);
            }
        }
    }
}

// ---------------- fused GRU + classifier --------------------------------
// 32-node tiles. 192 threads = 4 node-rows (8 nodes each) x 48 out-cols (8 each).
// Outputs o<192 -> gi = W_ih @ agg ; o>=192 -> gh = W_hh @ features.
#define XA_S  65
#define GS_S  388
#define HS_S  65
#define WO_S  65

__global__ __launch_bounds__(192) void gru_out_k(
    const float* __restrict__ feat,
    const float* __restrict__ W_ih, const float* __restrict__ W_hh,
    const float* __restrict__ b_ih, const float* __restrict__ b_hh,
    const float* __restrict__ W_out, const float* __restrict__ b_out,
    float* __restrict__ out)
{
    extern __shared__ float smf[];
    float* Wct = smf;                     // [64][384]   transposed combined W
    float* xa  = Wct + 64 * 384;          // [32][65]    agg tile
    float* xf  = xa + 32 * XA_S;          // [32][65]    feature tile
    float* gs  = xf + 32 * XA_S;          // [32][388]   gate pre-activations
    float* hs  = gs + 32 * GS_S;          // [32][65]    new hidden
    float* Wos = hs + 32 * HS_S;          // [16][65]    classifier W
    float* bos = Wos + 16 * WO_S;         // [16]

    int t   = threadIdx.x;
    int row = t & 3;       // nodes row*8 .. row*8+7
    int col = t >> 2;      // outputs col*8 .. col*8+7  (col<24 -> gi, else gh)

    // load W_ih / W_hh transposed into Wct[h][o] (lanes store consecutive o)
#pragma unroll
    for (int rep = 0; rep < 2; rep++) {
        int o = t + rep * 192;
        const float* wr = (o < 192) ? (W_ih + o * 64) : (W_hh + (o - 192) * 64);
        const float4* wr4 = reinterpret_cast<const float4*>(wr);
#pragma unroll
        for (int q = 0; q < 16; q++) {
            float4 v = wr4[q];
            int h = q * 4;
            Wct[(h    ) * 384 + o] = v.x;
            Wct[(h + 1) * 384 + o] = v.y;
            Wct[(h + 2) * 384 + o] = v.z;
            Wct[(h + 3) * 384 + o] = v.w;
        }
    }
    for (int k = t; k < 1024; k += 192) {
        int c = k >> 6, d = k & 63;
        Wos[c * WO_S + d] = W_out[k];
    }
    if (t < 16) bos[t] = b_out[t];

    float bias8[8];
#pragma unroll
    for (int i = 0; i < 8; i++) {
        int o = col * 8 + i;
        bias8[i] = (o < 192) ? b_ih[o] : b_hh[o - 192];
    }

    const int ntiles = NN / 32;  // 3125
    for (int tile = blockIdx.x; tile < ntiles; tile += gridDim.x) {
        int nb = tile * 32;
        __syncthreads();  // protect xa/xf/gs/hs from previous iteration readers
        for (int k = t; k < 2048; k += 192) {
            int nl = k >> 6, h = k & 63;
            size_t gidx = (size_t)(nb + nl) * 64 + h;
            xa[nl * XA_S + h] = g_agg[gidx];
            xf[nl * XA_S + h] = feat[gidx];
        }
        __syncthreads();

        float acc[8][8];
#pragma unroll
        for (int k = 0; k < 8; k++)
#pragma unroll
            for (int i = 0; i < 8; i++) acc[k][i] = bias8[i];

        const float* xin = (col < 24) ? xa : xf;
#pragma unroll 2
        for (int h = 0; h < 64; h++) {
            float4 w0 = *reinterpret_cast<const float4*>(&Wct[h * 384 + col * 8]);
            float4 w1 = *reinterpret_cast<const float4*>(&Wct[h * 384 + col * 8 + 4]);
            float wv[8] = {w0.x, w0.y, w0.z, w0.w, w1.x, w1.y, w1.z, w1.w};
            float xk[8];
#pragma unroll
            for (int k = 0; k < 8; k++) xk[k] = xin[(row * 8 + k) * XA_S + h];
#pragma unroll
            for (int k = 0; k < 8; k++)
#pragma unroll
                for (int i = 0; i < 8; i++) acc[k][i] = fmaf(xk[k], wv[i], acc[k][i]);
        }

#pragma unroll
        for (int k = 0; k < 8; k++) {
            float* gp = &gs[(row * 8 + k) * GS_S + col * 8];
            *reinterpret_cast<float4*>(gp)     = make_float4(acc[k][0], acc[k][1], acc[k][2], acc[k][3]);
            *reinterpret_cast<float4*>(gp + 4) = make_float4(acc[k][4], acc[k][5], acc[k][6], acc[k][7]);
        }
        __syncthreads();

        // GRU gates: r,z,n ordering (torch convention)
        for (int k = t; k < 2048; k += 192) {
            int nl = k >> 6, d = k & 63;
            const float* g = &gs[nl * GS_S];
            float ir = g[d],       iz = g[64 + d],  in_ = g[128 + d];
            float hr = g[192 + d], hz = g[256 + d], hn  = g[320 + d];
            float r = 1.f / (1.f + __expf(-(ir + hr)));
            float z = 1.f / (1.f + __expf(-(iz + hz)));
            float nng = tanhf(in_ + r * hn);
            hs[nl * HS_S + d] = (1.f - z) * nng + z * xf[nl * XA_S + d];
        }
        __syncthreads();

        // classifier: out[n][c] = b_out[c] + W_out[c,:] . h[n,:]
        for (int k = t; k < 512; k += 192) {
            int nl = k >> 4, c = k & 15;
            const float* wrow = &Wos[c * WO_S];
            const float* hrow = &hs[nl * HS_S];
            float s = bos[c];
#pragma unroll
            for (int d = 0; d < 64; d++) s = fmaf(wrow[d], hrow[d], s);
            out[(size_t)(nb + nl) * 16 + c] = s;
        }
    }
}

// ---------------- launch -------------------------------------------------
extern "C" void kernel_launch(void* const* d_in, const int* in_sizes, int n_in,
                              void* d_out, int out_size) {
    const float*         feat  = (const float*)d_in[0];
    const int*           src   = (const int*)d_in[1];
    const int*           dst   = (const int*)d_in[2];
    const unsigned char* types = (const unsigned char*)d_in[3];
    const float*         W0    = (const float*)d_in[4];
    const float*         b0    = (const float*)d_in[5];
    const float*         W1    = (const float*)d_in[6];
    const float*         b1    = (const float*)d_in[7];
    const float*         W_ih  = (const float*)d_in[8];
    const float*         W_hh  = (const float*)d_in[9];
    const float*         b_ih  = (const float*)d_in[10];
    const float*         b_hh  = (const float*)d_in[11];
    const float*         W_out = (const float*)d_in[12];
    const float*         b_out = (const float*)d_in[13];
    float*               out   = (float*)d_out;

    (void)in_sizes; (void)n_in; (void)out_size;

    void* aggp = nullptr; void* cntp = nullptr;
    cudaGetSymbolAddress(&aggp, g_agg);
    cudaGetSymbolAddress(&cntp, g_cnt);
    cudaMemsetAsync(aggp, 0, sizeof(float) * (size_t)NN * MD);
    cudaMemsetAsync(cntp, 0, sizeof(int) * 4);

    int dev = 0, numSM = 148;
    cudaGetDevice(&dev);
    cudaDeviceGetAttribute(&numSM, cudaDevAttrMultiProcessorCount, dev);

    detect_k<<<1, 256>>>(types);
    partition_k<<<(NE + 255) / 256, 256>>>(types);
    pad_k<<<1, 64>>>();

    int egrid = numSM * 6;
    edge_msg_k<<<egrid, 128>>>(feat, src, dst, W0, b0, 0);  // type==true  -> W0/b0
    edge_msg_k<<<egrid, 128>>>(feat, src, dst, W1, b1, 1);  // type==false -> W1/b1

    const size_t smBytes =
        (size_t)(64 * 384 + 2 * 32 * XA_S + 32 * GS_S + 32 * HS_S + 16 * WO_S + 16) * 4;
    cudaFuncSetAttribute(gru_out_k, cudaFuncAttributeMaxDynamicSharedMemorySize,
                         (int)smBytes);
    gru_out_k<<<numSM, 192, smBytes>>>(feat, W_ih, W_hh, b_ih, b_hh, W_out, b_out, out);
}

// round 13
// speedup vs baseline: 1.0039x; 1.0006x over previous
#include <cuda_runtime.h>
#include <cstdint>
#include <cstddef>

#define NN 100000
#define NE 1000000
#define HD 64
#define MD 64
#define NC 16

// ---------------- device scratch (no allocations allowed) ----------------
__device__ float g_agg[(size_t)NN * MD];   // 25.6 MB message accumulator
__device__ int   g_permA[NE];              // edges with type == true  (W0/b0)
__device__ int   g_permB[NE];              // edges with type == false (W1/b1)
__device__ int   g_cnt[4];                 // [0]=cntA [1]=cntB [2]=tilesA [3]=tilesB
__device__ int   g_is_byte;                // 1 if edge_types is 1-byte, 0 if int32

// ---------------- detect edge_types element width ------------------------
// bool(1B): ~50% of ALL bytes nonzero. int32(0/1): bytes at off%4!=0 are ALL 0.
// Reading 64KB as bytes is in-bounds under both interpretations (E=1e6 >= 65536).
__global__ void detect_k(const unsigned char* __restrict__ types) {
    __shared__ int found;
    if (threadIdx.x == 0) found = 0;
    __syncthreads();
    int loc = 0;
    for (int i = threadIdx.x; i < 65536; i += blockDim.x)
        if ((i & 3) != 0 && types[i] != 0) loc = 1;
    if (loc) found = 1;
    __syncthreads();
    if (threadIdx.x == 0) g_is_byte = found;
}

// ---------------- partition edges by type (warp-aggregated atomics) ------
__global__ void partition_k(const unsigned char* __restrict__ types) {
    int e = blockIdx.x * blockDim.x + threadIdx.x;
    bool valid = e < NE;
    int isb = g_is_byte;  // uniform
    bool ty = false;
    if (valid) {
        if (isb) ty = types[e] != 0;
        else     ty = reinterpret_cast<const int*>(types)[e] != 0;
    }
    unsigned mA = __ballot_sync(0xffffffffu, valid && ty);
    unsigned mB = __ballot_sync(0xffffffffu, valid && !ty);
    int lane = threadIdx.x & 31;
    int bA = 0, bB = 0;
    if (lane == 0) {
        bA = atomicAdd(&g_cnt[0], __popc(mA));
        bB = atomicAdd(&g_cnt[1], __popc(mB));
    }
    bA = __shfl_sync(0xffffffffu, bA, 0);
    bB = __shfl_sync(0xffffffffu, bB, 0);
    unsigned lt = (1u << lane) - 1u;
    if (valid) {
        if (ty) g_permA[bA + __popc(mA & lt)] = e;
        else    g_permB[bB + __popc(mB & lt)] = e;
    }
}

// pad each partition to a multiple of 64 with -1 sentinels; publish tile counts
__global__ void pad_k() {
    int t = threadIdx.x;  // 64 threads
    int cA = g_cnt[0], cB = g_cnt[1];
    int pA = (cA + 63) & ~63;   // NE % 64 == 0 so pA,pB <= NE
    int pB = (cB + 63) & ~63;
    if (cA + t < pA) g_permA[cA + t] = -1;
    if (cB + t < pB) g_permB[cB + t] = -1;
    if (t == 0) { g_cnt[2] = pA >> 6; g_cnt[3] = pB >> 6; }
}

// ---------------- edge message GEMM + scatter-add -----------------------
// One 64-edge tile per block iteration. 128 threads = 16 edge-rows x 8 out-cols.
// Thread computes 4 edges x 8 outputs (register blocked, 1.5 B LDS per FMA).
__global__ __launch_bounds__(128) void edge_msg_k(
    const float* __restrict__ feat, const int* __restrict__ src,
    const int* __restrict__ dst, const float* __restrict__ W,
    const float* __restrict__ b, int which)
{
    const int* perm = which ? g_permB : g_permA;
    int ntiles = g_cnt[which ? 3 : 2];
    if ((int)blockIdx.x >= ntiles) return;

    __shared__ float Wt[64][64];   // Wt[h][m]  (transposed weight)
    __shared__ float xs[64][64];   // xs[h][e]  (transposed gathered features)
    __shared__ int   eidx[64];
    __shared__ int   edst[64];

    int t   = threadIdx.x;
    int row = t & 15;        // edge group: edges row*4 .. row*4+3
    int col = t >> 4;        // output group: m = col*8 .. col*8+7

    // transpose W[m][h] -> Wt[h][m] (conflict-free: lanes store consecutive m)
    {
        int m = t & 63, hh = (t >> 6) * 32;
        const float4* wr = reinterpret_cast<const float4*>(W + m * 64 + hh);
#pragma unroll
        for (int q = 0; q < 8; q++) {
            float4 v = wr[q];
            int h = hh + q * 4;
            Wt[h][m] = v.x; Wt[h + 1][m] = v.y; Wt[h + 2][m] = v.z; Wt[h + 3][m] = v.w;
        }
    }
    float bias[8];
#pragma unroll
    for (int i = 0; i < 8; i++) bias[i] = b[col * 8 + i];

    for (int tile = blockIdx.x; tile < ntiles; tile += gridDim.x) {
        __syncthreads();   // protect eidx/xs from previous iteration readers
        if (t < 64) {
            int id = perm[tile * 64 + t];
            eidx[t] = id;
            edst[t] = (id >= 0) ? dst[id] : 0;
        }
        __syncthreads();

        // gather: thread covers edge e = t&63, h-half = (t>>6)*32, transposed store
        {
            int e = t & 63, hh = (t >> 6) * 32;
            int id = eidx[e];
            if (id >= 0) {
                const float4* xr =
                    reinterpret_cast<const float4*>(feat + (size_t)src[id] * 64 + hh);
#pragma unroll
                for (int q = 0; q < 8; q++) {
                    float4 v = xr[q];
                    int h = hh + q * 4;
                    xs[h][e] = v.x; xs[h + 1][e] = v.y; xs[h + 2][e] = v.z; xs[h + 3][e] = v.w;
                }
            } else {
#pragma unroll
                for (int q = 0; q < 8; q++) {
                    int h = hh + q * 4;
                    xs[h][e] = 0.f; xs[h + 1][e] = 0.f; xs[h + 2][e] = 0.f; xs[h + 3][e] = 0.f;
                }
            }
        }
        __syncthreads();

        float acc[4][8];
#pragma unroll
        for (int j = 0; j < 4; j++)
#pragma unroll
            for (int i = 0; i < 8; i++) acc[j][i] = bias[i];

#pragma unroll 4
        for (int h = 0; h < 64; h++) {
            float4 xv = *reinterpret_cast<const float4*>(&xs[h][row * 4]);
            float4 w0 = *reinterpret_cast<const float4*>(&Wt[h][col * 8]);
            float4 w1 = *reinterpret_cast<const float4*>(&Wt[h][col * 8 + 4]);
            float xj[4] = {xv.x, xv.y, xv.z, xv.w};
            float wi[8] = {w0.x, w0.y, w0.z, w0.w, w1.x, w1.y, w1.z, w1.w};
#pragma unroll
            for (int j = 0; j < 4; j++)
#pragma unroll
                for (int i = 0; i < 8; i++) acc[j][i] = fmaf(xj[j], wi[i], acc[j][i]);
        }

        // scatter-add into node accumulator (RED.ADD, result unused)
#pragma unroll
        for (int j = 0; j < 4; j++) {
            int e = row * 4 + j;
            if (eidx[e] >= 0) {
                float* p = g_agg + (size_t)edst[e] * 64 + col * 8;
#pragma unroll
                for (int i = 0; i < 8; i++) atomicAdd(p + i, acc[j][i]);
            }
        }
    }
}

// ---------------- fused GRU + classifier --------------------------------
// 32-node tiles. 192 threads = 4 node-rows (8 nodes each) x 48 out-cols (8 each).
// Outputs o<192 -> gi = W_ih @ agg ; o>=192 -> gh = W_hh @ features.
#define XA_S  65
#define GS_S  388
#define HS_S  65
#define WO_S  65

__global__ __launch_bounds__(192) void gru_out_k(
    const float* __restrict__ feat,
    const float* __restrict__ W_ih, const float* __restrict__ W_hh,
    const float* __restrict__ b_ih, const float* __restrict__ b_hh,
    const float* __restrict__ W_out, const float* __restrict__ b_out,
    float* __restrict__ out)
{
    extern __shared__ float smf[];
    float* Wct = smf;                     // [64][384]   transposed combined W
    float* xa  = Wct + 64 * 384;          // [32][65]    agg tile
    float* xf  = xa + 32 * XA_S;          // [32][65]    feature tile
    float* gs  = xf + 32 * XA_S;          // [32][388]   gate pre-activations
    float* hs  = gs + 32 * GS_S;          // [32][65]    new hidden
    float* Wos = hs + 32 * HS_S;          // [16][65]    classifier W
    float* bos = Wos + 16 * WO_S;         // [16]

    int t   = threadIdx.x;
    int row = t & 3;       // nodes row*8 .. row*8+7
    int col = t >> 2;      // outputs col*8 .. col*8+7  (col<24 -> gi, else gh)

    // load W_ih / W_hh transposed into Wct[h][o] (lanes store consecutive o)
#pragma unroll
    for (int rep = 0; rep < 2; rep++) {
        int o = t + rep * 192;
        const float* wr = (o < 192) ? (W_ih + o * 64) : (W_hh + (o - 192) * 64);
        const float4* wr4 = reinterpret_cast<const float4*>(wr);
#pragma unroll
        for (int q = 0; q < 16; q++) {
            float4 v = wr4[q];
            int h = q * 4;
            Wct[(h    ) * 384 + o] = v.x;
            Wct[(h + 1) * 384 + o] = v.y;
            Wct[(h + 2) * 384 + o] = v.z;
            Wct[(h + 3) * 384 + o] = v.w;
        }
    }
    for (int k = t; k < 1024; k += 192) {
        int c = k >> 6, d = k & 63;
        Wos[c * WO_S + d] = W_out[k];
    }
    if (t < 16) bos[t] = b_out[t];

    float bias8[8];
#pragma unroll
    for (int i = 0; i < 8; i++) {
        int o = col * 8 + i;
        bias8[i] = (o < 192) ? b_ih[o] : b_hh[o - 192];
    }

    const int ntiles = NN / 32;  // 3125
    for (int tile = blockIdx.x; tile < ntiles; tile += gridDim.x) {
        int nb = tile * 32;
        __syncthreads();  // protect xa/xf/gs/hs from previous iteration readers
        for (int k = t; k < 2048; k += 192) {
            int nl = k >> 6, h = k & 63;
            size_t gidx = (size_t)(nb + nl) * 64 + h;
            xa[nl * XA_S + h] = g_agg[gidx];
            xf[nl * XA_S + h] = feat[gidx];
        }
        __syncthreads();

        float acc[8][8];
#pragma unroll
        for (int k = 0; k < 8; k++)
#pragma unroll
            for (int i = 0; i < 8; i++) acc[k][i] = bias8[i];

        const float* xin = (col < 24) ? xa : xf;
#pragma unroll 2
        for (int h = 0; h < 64; h++) {
            float4 w0 = *reinterpret_cast<const float4*>(&Wct[h * 384 + col * 8]);
            float4 w1 = *reinterpret_cast<const float4*>(&Wct[h * 384 + col * 8 + 4]);
            float wv[8] = {w0.x, w0.y, w0.z, w0.w, w1.x, w1.y, w1.z, w1.w};
            float xk[8];
#pragma unroll
            for (int k = 0; k < 8; k++) xk[k] = xin[(row * 8 + k) * XA_S + h];
#pragma unroll
            for (int k = 0; k < 8; k++)
#pragma unroll
                for (int i = 0; i < 8; i++) acc[k][i] = fmaf(xk[k], wv[i], acc[k][i]);
        }

#pragma unroll
        for (int k = 0; k < 8; k++) {
            float* gp = &gs[(row * 8 + k) * GS_S + col * 8];
            *reinterpret_cast<float4*>(gp)     = make_float4(acc[k][0], acc[k][1], acc[k][2], acc[k][3]);
            *reinterpret_cast<float4*>(gp + 4) = make_float4(acc[k][4], acc[k][5], acc[k][6], acc[k][7]);
        }
        __syncthreads();

        // GRU gates: r,z,n ordering (torch convention)
        for (int k = t; k < 2048; k += 192) {
            int nl = k >> 6, d = k & 63;
            const float* g = &gs[nl * GS_S];
            float ir = g[d],       iz = g[64 + d],  in_ = g[128 + d];
            float hr = g[192 + d], hz = g[256 + d], hn  = g[320 + d];
            float r = 1.f / (1.f + __expf(-(ir + hr)));
            float z = 1.f / (1.f + __expf(-(iz + hz)));
            float nng = tanhf(in_ + r * hn);
            hs[nl * HS_S + d] = (1.f - z) * nng + z * xf[nl * XA_S + d];
        }
        __syncthreads();

        // classifier: out[n][c] = b_out[c] + W_out[c,:] . h[n,:]
        for (int k = t; k < 512; k += 192) {
            int nl = k >> 4, c = k & 15;
            const float* wrow = &Wos[c * WO_S];
            const float* hrow = &hs[nl * HS_S];
            float s = bos[c];
#pragma unroll
            for (int d = 0; d < 64; d++) s = fmaf(wrow[d], hrow[d], s);
            out[(size_t)(nb + nl) * 16 + c] = s;
        }
    }
}

// ---------------- launch -------------------------------------------------
extern "C" void kernel_launch(void* const* d_in, const int* in_sizes, int n_in,
                              void* d_out, int out_size) {
    const float*         feat  = (const float*)d_in[0];
    const int*           src   = (const int*)d_in[1];
    const int*           dst   = (const int*)d_in[2];
    const unsigned char* types = (const unsigned char*)d_in[3];
    const float*         W0    = (const float*)d_in[4];
    const float*         b0    = (const float*)d_in[5];
    const float*         W1    = (const float*)d_in[6];
    const float*         b1    = (const float*)d_in[7];
    const float*         W_ih  = (const float*)d_in[8];
    const float*         W_hh  = (const float*)d_in[9];
    const float*         b_ih  = (const float*)d_in[10];
    const float*         b_hh  = (const float*)d_in[11];
    const float*         W_out = (const float*)d_in[12];
    const float*         b_out = (const float*)d_in[13];
    float*               out   = (float*)d_out;

    (void)in_sizes; (void)n_in; (void)out_size;

    void* aggp = nullptr; void* cntp = nullptr;
    cudaGetSymbolAddress(&aggp, g_agg);
    cudaGetSymbolAddress(&cntp, g_cnt);
    cudaMemsetAsync(aggp, 0, sizeof(float) * (size_t)NN * MD);
    cudaMemsetAsync(cntp, 0, sizeof(int) * 4);

    int dev = 0, numSM = 148;
    cudaGetDevice(&dev);
    cudaDeviceGetAttribute(&numSM, cudaDevAttrMultiProcessorCount, dev);

    detect_k<<<1, 256>>>(types);
    partition_k<<<(NE + 255) / 256, 256>>>(types);
    pad_k<<<1, 64>>>();

    int egrid = numSM * 6;
    edge_msg_k<<<egrid, 128>>>(feat, src, dst, W0, b0, 0);  // type==true  -> W0/b0
    edge_msg_k<<<egrid, 128>>>(feat, src, dst, W1, b1, 1);  // type==false -> W1/b1

    const size_t smBytes =
        (size_t)(64 * 384 + 2 * 32 * XA_S + 32 * GS_S + 32 * HS_S + 16 * WO_S + 16) * 4;
    cudaFuncSetAttribute(gru_out_k, cudaFuncAttributeMaxDynamicSharedMemorySize,
                         (int)smBytes);
    gru_out_k<<<numSM, 192, smBytes>>>(feat, W_ih, W_hh, b_ih, b_hh, W_out, b_out, out);
}

// round 16
// speedup vs baseline: 1.2207x; 1.2159x over previous
#include <cuda_runtime.h>
#include <cstdint>
#include <cstddef>

#define NN 100000
#define NE 1000000
#define HD 64
#define MD 64
#define NC 16

// ---------------- device scratch (no allocations allowed) ----------------
__device__ float g_agg[(size_t)NN * MD];    // 25.6 MB message accumulator
__device__ float g_gs[(size_t)NN * 384];    // 153.6 MB gate pre-activations
__device__ int   g_permA[NE];               // edges with type == true  (W0/b0)
__device__ int   g_permB[NE];               // edges with type == false (W1/b1)
__device__ int   g_cnt[4];                  // [0]=cntA [1]=cntB [2]=tilesA [3]=tilesB
__device__ int   g_is_byte;                 // 1 if edge_types is 1-byte, 0 if int32

// ---------------- detect edge_types element width ------------------------
// bool(1B): ~50% of ALL bytes nonzero. int32(0/1): bytes at off%4!=0 are ALL 0.
__global__ void detect_k(const unsigned char* __restrict__ types) {
    __shared__ int found;
    if (threadIdx.x == 0) found = 0;
    __syncthreads();
    int loc = 0;
    for (int i = threadIdx.x; i < 65536; i += blockDim.x)
        if ((i & 3) != 0 && types[i] != 0) loc = 1;
    if (loc) found = 1;
    __syncthreads();
    if (threadIdx.x == 0) g_is_byte = found;
}

// ---------------- partition edges by type (warp-aggregated atomics) ------
__global__ void partition_k(const unsigned char* __restrict__ types) {
    int e = blockIdx.x * blockDim.x + threadIdx.x;
    bool valid = e < NE;
    int isb = g_is_byte;  // uniform
    bool ty = false;
    if (valid) {
        if (isb) ty = types[e] != 0;
        else     ty = reinterpret_cast<const int*>(types)[e] != 0;
    }
    unsigned mA = __ballot_sync(0xffffffffu, valid && ty);
    unsigned mB = __ballot_sync(0xffffffffu, valid && !ty);
    int lane = threadIdx.x & 31;
    int bA = 0, bB = 0;
    if (lane == 0) {
        bA = atomicAdd(&g_cnt[0], __popc(mA));
        bB = atomicAdd(&g_cnt[1], __popc(mB));
    }
    bA = __shfl_sync(0xffffffffu, bA, 0);
    bB = __shfl_sync(0xffffffffu, bB, 0);
    unsigned lt = (1u << lane) - 1u;
    if (valid) {
        if (ty) g_permA[bA + __popc(mA & lt)] = e;
        else    g_permB[bB + __popc(mB & lt)] = e;
    }
}

// pad each partition to a multiple of 64 with -1 sentinels; publish tile counts
__global__ void pad_k() {
    int t = threadIdx.x;  // 64 threads
    int cA = g_cnt[0], cB = g_cnt[1];
    int pA = (cA + 63) & ~63;
    int pB = (cB + 63) & ~63;
    if (cA + t < pA) g_permA[cA + t] = -1;
    if (cB + t < pB) g_permB[cB + t] = -1;
    if (t == 0) { g_cnt[2] = pA >> 6; g_cnt[3] = pB >> 6; }
}

// ---------------- edge message GEMM + scatter-add -----------------------
// Both partitions in one launch: even blocks -> partition A, odd -> B.
// 64-edge tiles, 128 threads = 16 edge-rows x 8 out-cols; thread = 4 edges x 8 outs.
// Scatter via atomicAdd(float4*) -> RED.128 (4x fewer LSU ops than scalar).
__global__ __launch_bounds__(128) void edge_msg_k(
    const float* __restrict__ feat, const int* __restrict__ src,
    const int* __restrict__ dst,
    const float* __restrict__ W0, const float* __restrict__ b0,
    const float* __restrict__ W1, const float* __restrict__ b1)
{
    int which = blockIdx.x & 1;
    const int*   perm = which ? g_permB : g_permA;
    int          ntiles = g_cnt[which ? 3 : 2];
    const float* W = which ? W1 : W0;
    const float* b = which ? b1 : b0;

    __shared__ float Wt[64][64];   // Wt[h][m]
    __shared__ float xs[64][64];   // xs[h][e]
    __shared__ int   svalid[64];
    __shared__ int   ssrc[64];
    __shared__ int   sdst[64];

    int t   = threadIdx.x;
    int row = t & 15;        // edges row*4 .. row*4+3
    int col = t >> 4;        // outputs col*8 .. col*8+7

    // transpose W[m][h] -> Wt[h][m]
    {
        int m = t & 63, hh = (t >> 6) * 32;
        const float4* wr = reinterpret_cast<const float4*>(W + m * 64 + hh);
#pragma unroll
        for (int q = 0; q < 8; q++) {
            float4 v = wr[q];
            int h = hh + q * 4;
            Wt[h][m] = v.x; Wt[h + 1][m] = v.y; Wt[h + 2][m] = v.z; Wt[h + 3][m] = v.w;
        }
    }
    float bias[8];
#pragma unroll
    for (int i = 0; i < 8; i++) bias[i] = b[col * 8 + i];

    for (int tile = (int)(blockIdx.x >> 1); tile < ntiles; tile += (int)(gridDim.x >> 1)) {
        __syncthreads();   // protect smem from previous iteration readers
        if (t < 64) {
            int id = perm[tile * 64 + t];
            svalid[t] = id;
            ssrc[t] = (id >= 0) ? src[id] : 0;
            sdst[t] = (id >= 0) ? dst[id] : 0;
        }
        __syncthreads();

        // gather: thread covers edge e = t&63, h-half = (t>>6)*32
        {
            int e = t & 63, hh = (t >> 6) * 32;
            if (svalid[e] >= 0) {
                const float4* xr =
                    reinterpret_cast<const float4*>(feat + (size_t)ssrc[e] * 64 + hh);
#pragma unroll
                for (int q = 0; q < 8; q++) {
                    float4 v = xr[q];
                    int h = hh + q * 4;
                    xs[h][e] = v.x; xs[h + 1][e] = v.y; xs[h + 2][e] = v.z; xs[h + 3][e] = v.w;
                }
            } else {
#pragma unroll
                for (int q = 0; q < 8; q++) {
                    int h = hh + q * 4;
                    xs[h][e] = 0.f; xs[h + 1][e] = 0.f; xs[h + 2][e] = 0.f; xs[h + 3][e] = 0.f;
                }
            }
        }
        __syncthreads();

        float acc[4][8];
#pragma unroll
        for (int j = 0; j < 4; j++)
#pragma unroll
            for (int i = 0; i < 8; i++) acc[j][i] = bias[i];

#pragma unroll 4
        for (int h = 0; h < 64; h++) {
            float4 xv = *reinterpret_cast<const float4*>(&xs[h][row * 4]);
            float4 w0 = *reinterpret_cast<const float4*>(&Wt[h][col * 8]);
            float4 w1 = *reinterpret_cast<const float4*>(&Wt[h][col * 8 + 4]);
            float xj[4] = {xv.x, xv.y, xv.z, xv.w};
            float wi[8] = {w0.x, w0.y, w0.z, w0.w, w1.x, w1.y, w1.z, w1.w};
#pragma unroll
            for (int j = 0; j < 4; j++)
#pragma unroll
                for (int i = 0; i < 8; i++) acc[j][i] = fmaf(xj[j], wi[i], acc[j][i]);
        }

        // scatter-add: 2 x RED.128 per edge per thread
#pragma unroll
        for (int j = 0; j < 4; j++) {
            int e = row * 4 + j;
            if (svalid[e] >= 0) {
                float4* p = reinterpret_cast<float4*>(
                    g_agg + (size_t)sdst[e] * 64 + col * 8);
                atomicAdd(p,     make_float4(acc[j][0], acc[j][1], acc[j][2], acc[j][3]));
                atomicAdd(p + 1, make_float4(acc[j][4], acc[j][5], acc[j][6], acc[j][7]));
            }
        }
    }
}

// ---------------- GRU gate GEMM: gs[N,384] = [agg|feat] @ [W_ih|W_hh]^T + b --
// Column-block cb in 0..5 (cb<3: gi from g_agg/W_ih; cb>=3: gh from feat/W_hh).
// 64-node tiles, 128 threads = 16 node-rows x 8 out-cols; thread = 4 nodes x 8 outs.
__global__ __launch_bounds__(128) void gru_gemm_k(
    const float* __restrict__ feat,
    const float* __restrict__ W_ih, const float* __restrict__ W_hh,
    const float* __restrict__ b_ih, const float* __restrict__ b_hh)
{
    int cb = (int)(blockIdx.x % 6);
    const float* Wsrc = (cb < 3) ? (W_ih + (size_t)cb * 64 * 64)
                                 : (W_hh + (size_t)(cb - 3) * 64 * 64);
    const float* bsrc = (cb < 3) ? (b_ih + cb * 64) : (b_hh + (cb - 3) * 64);
    const float* xin  = (cb < 3) ? g_agg : feat;

    __shared__ float Wt[64][64];   // Wt[h][o_local]
    __shared__ float xs[64][64];   // xs[h][node_local]

    int t   = threadIdx.x;
    int row = t & 15;
    int col = t >> 4;

    {
        int m = t & 63, hh = (t >> 6) * 32;
        const float4* wr = reinterpret_cast<const float4*>(Wsrc + m * 64 + hh);
#pragma unroll
        for (int q = 0; q < 8; q++) {
            float4 v = wr[q];
            int h = hh + q * 4;
            Wt[h][m] = v.x; Wt[h + 1][m] = v.y; Wt[h + 2][m] = v.z; Wt[h + 3][m] = v.w;
        }
    }
    float bias[8];
#pragma unroll
    for (int i = 0; i < 8; i++) bias[i] = bsrc[col * 8 + i];

    const int NT = (NN + 63) / 64;  // 1563 (last tile partial: 32 nodes)
    int bstride = (int)(gridDim.x / 6);
    for (int tile = (int)(blockIdx.x / 6); tile < NT; tile += bstride) {
        int nb = tile * 64;
        __syncthreads();

        // load input tile (coalesced rows), zero-fill past NN
        {
            int e = t & 63, hh = (t >> 6) * 32;
            if (nb + e < NN) {
                const float4* xr =
                    reinterpret_cast<const float4*>(xin + (size_t)(nb + e) * 64 + hh);
#pragma unroll
                for (int q = 0; q < 8; q++) {
                    float4 v = xr[q];
                    int h = hh + q * 4;
                    xs[h][e] = v.x; xs[h + 1][e] = v.y; xs[h + 2][e] = v.z; xs[h + 3][e] = v.w;
                }
            } else {
#pragma unroll
                for (int q = 0; q < 8; q++) {
                    int h = hh + q * 4;
                    xs[h][e] = 0.f; xs[h + 1][e] = 0.f; xs[h + 2][e] = 0.f; xs[h + 3][e] = 0.f;
                }
            }
        }
        __syncthreads();

        float acc[4][8];
#pragma unroll
        for (int j = 0; j < 4; j++)
#pragma unroll
            for (int i = 0; i < 8; i++) acc[j][i] = bias[i];

#pragma unroll 4
        for (int h = 0; h < 64; h++) {
            float4 xv = *reinterpret_cast<const float4*>(&xs[h][row * 4]);
            float4 w0 = *reinterpret_cast<const float4*>(&Wt[h][col * 8]);
            float4 w1 = *reinterpret_cast<const float4*>(&Wt[h][col * 8 + 4]);
            float xj[4] = {xv.x, xv.y, xv.z, xv.w};
            float wi[8] = {w0.x, w0.y, w0.z, w0.w, w1.x, w1.y, w1.z, w1.w};
#pragma unroll
            for (int j = 0; j < 4; j++)
#pragma unroll
                for (int i = 0; i < 8; i++) acc[j][i] = fmaf(xj[j], wi[i], acc[j][i]);
        }

#pragma unroll
        for (int j = 0; j < 4; j++) {
            int n = nb + row * 4 + j;
            if (n < NN) {
                float* gp = g_gs + (size_t)n * 384 + cb * 64 + col * 8;
                *reinterpret_cast<float4*>(gp) =
                    make_float4(acc[j][0], acc[j][1], acc[j][2], acc[j][3]);
                *reinterpret_cast<float4*>(gp + 4) =
                    make_float4(acc[j][4], acc[j][5], acc[j][6], acc[j][7]);
            }
        }
    }
}

// ---------------- fused GRU gates + classifier ---------------------------
// Block = 8 nodes, 128 threads: thread (j = t>>4 node, q = t&15) owns 4 dims.
#define HSX 68
__global__ __launch_bounds__(128) void gates_k(
    const float* __restrict__ feat,
    const float* __restrict__ W_out, const float* __restrict__ b_out,
    float* __restrict__ out)
{
    __shared__ float hs[8][HSX];
    __shared__ float Wos[16][65];
    __shared__ float bos[16];

    int t = threadIdx.x;
    // load classifier weights: 16 rows x 8 threads, each thread 8 floats
    {
        int c = t >> 3, part = t & 7;
        const float4* wr = reinterpret_cast<const float4*>(W_out + c * 64 + part * 8);
        float4 v0 = wr[0], v1 = wr[1];
        float* d = &Wos[c][part * 8];
        d[0] = v0.x; d[1] = v0.y; d[2] = v0.z; d[3] = v0.w;
        d[4] = v1.x; d[5] = v1.y; d[6] = v1.z; d[7] = v1.w;
    }
    if (t < 16) bos[t] = b_out[t];

    int nb = (int)blockIdx.x * 8;
    int j = t >> 4, q = t & 15;
    int n = nb + j;

    const float* g = g_gs + (size_t)n * 384 + q * 4;
    float4 ir = *reinterpret_cast<const float4*>(g);
    float4 iz = *reinterpret_cast<const float4*>(g + 64);
    float4 in_ = *reinterpret_cast<const float4*>(g + 128);
    float4 hr = *reinterpret_cast<const float4*>(g + 192);
    float4 hz = *reinterpret_cast<const float4*>(g + 256);
    float4 hn = *reinterpret_cast<const float4*>(g + 320);
    float4 f  = *reinterpret_cast<const float4*>(feat + (size_t)n * 64 + q * 4);

    float irs[4] = {ir.x, ir.y, ir.z, ir.w};
    float izs[4] = {iz.x, iz.y, iz.z, iz.w};
    float ins[4] = {in_.x, in_.y, in_.z, in_.w};
    float hrs[4] = {hr.x, hr.y, hr.z, hr.w};
    float hzs[4] = {hz.x, hz.y, hz.z, hz.w};
    float hns[4] = {hn.x, hn.y, hn.z, hn.w};
    float fs[4]  = {f.x, f.y, f.z, f.w};

#pragma unroll
    for (int k = 0; k < 4; k++) {
        float r = 1.f / (1.f + __expf(-(irs[k] + hrs[k])));
        float z = 1.f / (1.f + __expf(-(izs[k] + hzs[k])));
        float nng = tanhf(ins[k] + r * hns[k]);
        hs[j][q * 4 + k] = (1.f - z) * nng + z * fs[k];
    }
    __syncthreads();

    // classifier: thread = (node j2, class c)
    int j2 = t >> 4, c = t & 15;
    const float* hrow = hs[j2];
    const float* wrow = Wos[c];
    float s = bos[c];
#pragma unroll
    for (int d = 0; d < 64; d++) s = fmaf(wrow[d], hrow[d], s);
    out[(size_t)(nb + j2) * 16 + c] = s;
}

// ---------------- launch -------------------------------------------------
extern "C" void kernel_launch(void* const* d_in, const int* in_sizes, int n_in,
                              void* d_out, int out_size) {
    const float*         feat  = (const float*)d_in[0];
    const int*           src   = (const int*)d_in[1];
    const int*           dst   = (const int*)d_in[2];
    const unsigned char* types = (const unsigned char*)d_in[3];
    const float*         W0    = (const float*)d_in[4];
    const float*         b0    = (const float*)d_in[5];
    const float*         W1    = (const float*)d_in[6];
    const float*         b1    = (const float*)d_in[7];
    const float*         W_ih  = (const float*)d_in[8];
    const float*         W_hh  = (const float*)d_in[9];
    const float*         b_ih  = (const float*)d_in[10];
    const float*         b_hh  = (const float*)d_in[11];
    const float*         W_out = (const float*)d_in[12];
    const float*         b_out = (const float*)d_in[13];
    float*               out   = (float*)d_out;

    (void)in_sizes; (void)n_in; (void)out_size;

    void* aggp = nullptr; void* cntp = nullptr;
    cudaGetSymbolAddress(&aggp, g_agg);
    cudaGetSymbolAddress(&cntp, g_cnt);
    cudaMemsetAsync(aggp, 0, sizeof(float) * (size_t)NN * MD);
    cudaMemsetAsync(cntp, 0, sizeof(int) * 4);

    int dev = 0, numSM = 148;
    cudaGetDevice(&dev);
    cudaDeviceGetAttribute(&numSM, cudaDevAttrMultiProcessorCount, dev);

    detect_k<<<1, 256>>>(types);
    partition_k<<<(NE + 255) / 256, 256>>>(types);
    pad_k<<<1, 64>>>();

    // both partitions in one launch (even blocks -> A, odd -> B)
    edge_msg_k<<<numSM * 6, 128>>>(feat, src, dst, W0, b0, W1, b1);

    // GRU gate pre-activations (6 column-blocks x numSM persistent blocks)
    gru_gemm_k<<<numSM * 6, 128>>>(feat, W_ih, W_hh, b_ih, b_hh);

    // gates + classifier
    gates_k<<<NN / 8, 128>>>(feat, W_out, b_out, out);
}